// round 14
// baseline (speedup 1.0000x reference)
#include <cuda_runtime.h>
#include <math.h>

// Shapes (hardcoded from reference setup_inputs)
#define Bn   64
#define Nn   1025
#define Dn   1024
#define Cn   64
#define TOT  (Bn * Nn)   // 65600 rows; row r <-> (b=r/Nn, n=r%Nn), g_h[r*64+c]

// Scratch (device globals; no runtime allocation)
__device__ __align__(16) float g_y[(size_t)TOT * Dn];         // LN+gamma-mix output (row-major [r][1024])
__device__ __align__(16) float g_h[(size_t)TOT * Cn];         // post GEMM1      (B,N,C)
__device__ __align__(16) float g_sp[(size_t)Bn * 1024 * Cn];  // post depthwise  (B,HW,C)
__device__ __align__(16) float g_act[(size_t)TOT * Cn];       // post proj+gelu  (B,N,C)

// ---------- packed f32x2 helpers ----------
static __device__ __forceinline__ unsigned long long pk2(float a, float b) {
    unsigned long long r;
    asm("mov.b64 %0, {%1,%2};" : "=l"(r) : "f"(a), "f"(b));
    return r;
}
static __device__ __forceinline__ void upk2(unsigned long long v, float& a, float& b) {
    asm("mov.b64 {%0,%1}, %2;" : "=f"(a), "=f"(b) : "l"(v));
}
static __device__ __forceinline__ void fma2(unsigned long long& d, unsigned long long a,
                                            unsigned long long b) {
    asm("fma.rn.f32x2 %0, %1, %2, %0;" : "+l"(d) : "l"(a), "l"(b));
}
static __device__ __forceinline__ void add2(unsigned long long& d, unsigned long long a) {
    asm("add.rn.f32x2 %0, %0, %1;" : "+l"(d) : "l"(a));
}

static __device__ __forceinline__ float gelu_exact(float t) {
    return 0.5f * t * (1.0f + erff(t * 0.70710678118654752f));
}

// ======================================================================
// Kernel 1y: fused LN stats + y = (ln*gamma) + x*gammax  -> g_y[r][1024]
// One warp per row; single x read, single y write.
// ======================================================================
__global__ __launch_bounds__(256) void k1y_produce(
    const float* __restrict__ x, const float* __restrict__ lnw, const float* __restrict__ lnb,
    const float* __restrict__ gam, const float* __restrict__ gmx)
{
    const int r = blockIdx.x * 8 + (threadIdx.x >> 5);
    const int lane = threadIdx.x & 31;
    const int b = r / Nn, n = r - b * Nn;
    const float4* xp = (const float4*)(x + ((size_t)(n * Bn + b) << 10));

    float4 v[8];
    float s = 0.f, q = 0.f;
#pragma unroll
    for (int i = 0; i < 8; i++) {
        float4 t = xp[lane + 32 * i];
        v[i] = t;
        s += t.x + t.y + t.z + t.w;
        q += t.x * t.x + t.y * t.y + t.z * t.z + t.w * t.w;
    }
#pragma unroll
    for (int o = 16; o; o >>= 1) {
        s += __shfl_xor_sync(0xffffffffu, s, o);
        q += __shfl_xor_sync(0xffffffffu, q, o);
    }
    const float mu = s * (1.0f / 1024.0f);
    const float var = q * (1.0f / 1024.0f) - mu * mu;
    const float rs = rsqrtf(var + 1e-5f);

    float4* yp = (float4*)(g_y + (size_t)r * 1024);
#pragma unroll
    for (int i = 0; i < 8; i++) {
        const int f4 = lane + 32 * i;
        float4 t = v[i];
        float4 lw = ((const float4*)lnw)[f4];
        float4 lb = ((const float4*)lnb)[f4];
        float4 gm = ((const float4*)gam)[f4];
        float4 gx = ((const float4*)gmx)[f4];
        float4 o;
        o.x = ((t.x - mu) * rs * lw.x + lb.x) * gm.x + t.x * gx.x;
        o.y = ((t.y - mu) * rs * lw.y + lb.y) * gm.y + t.y * gx.y;
        o.z = ((t.z - mu) * rs * lw.z + lb.z) * gm.z + t.z * gx.z;
        o.w = ((t.w - mu) * rs * lw.w + lb.w) * gm.w + t.w * gx.w;
        yp[f4] = o;
    }
}

// ======================================================================
// Kernel 1g: streaming GEMM1 (g_y @ w1half + b1) -> g_h
// grid = 65 row-blocks x 2 col-halves. Block: w1[:, half] [1024k][32c]
// = 128KB smem loaded ONCE. Streams 1024 rows in 16 subtiles of 64;
// per subtile 8 K-chunks of 128 with register prefetch. 512 threads =
// 4 K-split groups x (8 rows x 2 cols tiles); per-subtile smem reduction.
// Weight L2 traffic: 2.1GB -> 33MB.
// ======================================================================
#define K1G_SMEM (128*1024 + 33792)

__global__ __launch_bounds__(512, 1) void k1g_gemm1(
    const float* __restrict__ w1, const float* __restrict__ b1)
{
    extern __shared__ __align__(16) char smg[];
    float* ws = (float*)smg;                           // [1024][32]
    float* ys = (float*)(smg + 128 * 1024);            // [128][66]
    unsigned long long* red = (unsigned long long*)(smg + 128 * 1024);  // 24KB, aliases ys

    const int tid = threadIdx.x;
    const int h = blockIdx.x & 1;
    const int rb = blockIdx.x >> 1;
    const int rowbase = rb << 10;
    const int remrows = TOT - rowbase;
    const int nsub = remrows >= 1024 ? 16 : (remrows >> 6);
    const int co = h * 32;

    // ---- load weight half once: ws[k][32] (fully coalesced, 128B-line aligned) ----
#pragma unroll
    for (int i = 0; i < 16; i++) {
        const int f = tid + 512 * i;                   // float4 index; k = f>>3, j = f&7
        ((float4*)ws)[f] = *(const float4*)(w1 + ((size_t)(f >> 3) << 6) + co + ((f & 7) << 2));
    }

    // loader role: row lr (0..63), k-16-block lq (0..7)  [STS conflict-free]
    const int lr = tid & 63, lq = tid >> 6;
    // GEMM role: kg = k-split group (32k each per 128-chunk), rg = 8-row group, cg = col pair
    const int kg = tid >> 7;
    const int t2 = tid & 127;
    const int rg = t2 >> 4;        // 0..7 -> rows rg*8..+7
    const int cg = t2 & 15;        // cols cg*2, cg*2+1
    const float2 b1v = *(const float2*)(b1 + co + cg * 2);

    for (int s = 0; s < nsub; s++) {
        const float* grow = g_y + ((size_t)(rowbase + s * 64 + lr) << 10);

        // prefetch chunk 0 into registers
        float4 pre[4];
#pragma unroll
        for (int i = 0; i < 4; i++)
            pre[i] = *(const float4*)(grow + lq * 16 + i * 4);

        unsigned long long acc[4][2];
#pragma unroll
        for (int p = 0; p < 4; p++) { acc[p][0] = 0ull; acc[p][1] = 0ull; }

        for (int kc = 0; kc < 8; kc++) {
            __syncthreads();   // ys/red free (prev compute or prev subtile's reduction done)

            // ---- store prefetched chunk to ys[k][66] ----
#pragma unroll
            for (int i = 0; i < 4; i++) {
                const int k0 = lq * 16 + i * 4;
                ys[(k0 + 0) * 66 + lr] = pre[i].x;
                ys[(k0 + 1) * 66 + lr] = pre[i].y;
                ys[(k0 + 2) * 66 + lr] = pre[i].z;
                ys[(k0 + 3) * 66 + lr] = pre[i].w;
            }
            __syncthreads();

            // ---- prefetch next chunk (latency hidden under compute) ----
            if (kc < 7) {
#pragma unroll
                for (int i = 0; i < 4; i++)
                    pre[i] = *(const float4*)(grow + (kc + 1) * 128 + lq * 16 + i * 4);
            }

            // ---- compute this kg-group's 32 k ----
            const float* wk = ws + (size_t)(kc * 128 + kg * 32) * 32 + cg * 2;
            const float* yk = ys + (kg * 32) * 66 + rg * 8;
#pragma unroll 8
            for (int kk = 0; kk < 32; kk++) {
                float2 wv = *(const float2*)(wk + kk * 32);
                unsigned long long w0 = pk2(wv.x, wv.x), w1d = pk2(wv.y, wv.y);
                const float* yr = yk + kk * 66;
                unsigned long long y0 = *(const unsigned long long*)(yr + 0);
                unsigned long long y1 = *(const unsigned long long*)(yr + 2);
                unsigned long long y2 = *(const unsigned long long*)(yr + 4);
                unsigned long long y3 = *(const unsigned long long*)(yr + 6);
                fma2(acc[0][0], y0, w0); fma2(acc[0][1], y0, w1d);
                fma2(acc[1][0], y1, w0); fma2(acc[1][1], y1, w1d);
                fma2(acc[2][0], y2, w0); fma2(acc[2][1], y2, w1d);
                fma2(acc[3][0], y3, w0); fma2(acc[3][1], y3, w1d);
            }
        }

        // ---- k-split reduction in smem (red aliases ys; ys content dead) ----
        __syncthreads();
        if (kg) {
#pragma unroll
            for (int p = 0; p < 4; p++) {
                red[(((kg - 1) * 128 + t2) << 3) + p * 2 + 0] = acc[p][0];
                red[(((kg - 1) * 128 + t2) << 3) + p * 2 + 1] = acc[p][1];
            }
        }
        __syncthreads();
        if (!kg) {
#pragma unroll
            for (int p = 0; p < 4; p++) {
#pragma unroll
                for (int g = 0; g < 3; g++) {
                    add2(acc[p][0], red[((g * 128 + t2) << 3) + p * 2 + 0]);
                    add2(acc[p][1], red[((g * 128 + t2) << 3) + p * 2 + 1]);
                }
                float e0, o0, e1, o1;
                upk2(acc[p][0], e0, o0);   // col cg*2   : rows (2p, 2p+1)
                upk2(acc[p][1], e1, o1);   // col cg*2+1 : rows (2p, 2p+1)
                const int rowe = rowbase + s * 64 + rg * 8 + 2 * p;
                float* d0 = g_h + ((size_t)rowe << 6) + co + cg * 2;
                *(float2*)d0 = make_float2(e0 + b1v.x, e1 + b1v.y);
                *(float2*)(d0 + 64) = make_float2(o0 + b1v.x, o1 + b1v.y);
            }
        }
    }
}

// ======================================================================
// Kernel 2: depthwise 3x3 + 5x5 + 7x7, averaged, + identity -> g_sp
// (proven R7/R10 version)
// ======================================================================
__global__ __launch_bounds__(256) void k2_dwconv(
    const float* __restrict__ w3, const float* __restrict__ b3,
    const float* __restrict__ w5, const float* __restrict__ b5,
    const float* __restrict__ w7, const float* __restrict__ b7)
{
    __shared__ __align__(16) float tile[38 * 38 * 4];
    __shared__ float wk[4 * 83];

    const int tid = threadIdx.x;
    const int cg = blockIdx.x;
    const int b = blockIdx.y;

    for (int i = tid; i < 4 * 83; i += 256) {
        int ch = i / 83, j = i - ch * 83;
        int c = cg * 4 + ch;
        float wv;
        if (j < 9)       wv = w3[c * 9 + j];
        else if (j < 34) wv = w5[c * 25 + (j - 9)];
        else             wv = w7[c * 49 + (j - 34)];
        wk[i] = wv;
    }

    const float* src = g_h + ((size_t)b * Nn + 1) * 64 + cg * 4;
    for (int idx = tid; idx < 38 * 38; idx += 256) {
        int rr = idx / 38, cc = idx - rr * 38;
        int gy = rr - 3, gxp = cc - 3;
        float4 val = make_float4(0.f, 0.f, 0.f, 0.f);
        if ((unsigned)gy < 32u && (unsigned)gxp < 32u)
            val = *(const float4*)(src + (size_t)(gy * 32 + gxp) * 64);
        *(float4*)&tile[idx * 4] = val;
    }
    __syncthreads();

    const int ch = tid & 3;
    const int col = (tid >> 2) & 31;
    const int row0 = (tid >> 7) * 16;

    float acc[16];
#pragma unroll
    for (int k = 0; k < 16; k++) acc[k] = 0.f;

    const float* wc = wk + ch * 83;

#define CONV_TAPS(RAD, WOFF, KS)                                                   \
    for (int dy = -(RAD); dy <= (RAD); dy++) {                                     \
        for (int dx = -(RAD); dx <= (RAD); dx++) {                                 \
            float wv = wc[(WOFF) + (dy + (RAD)) * (KS) + (dx + (RAD))];            \
            const float* tp = tile + (((row0 + 3 + dy) * 38) + (col + 3 + dx)) * 4 + ch; \
            _Pragma("unroll")                                                      \
            for (int k = 0; k < 16; k++) acc[k] += tp[k * 152] * wv;               \
        }                                                                          \
    }

    CONV_TAPS(1, 0, 3)
    CONV_TAPS(2, 9, 5)
    CONV_TAPS(3, 34, 7)
#undef CONV_TAPS

    const int c = cg * 4 + ch;
    const float bsum = (b3[c] + b5[c] + b7[c]) * (1.0f / 3.0f);
    float* dst = g_sp + ((size_t)b * 1024) * 64 + c;
    const float* ctr = tile + ((row0 + 3) * 38 + col + 3) * 4 + ch;
#pragma unroll
    for (int k = 0; k < 16; k++) {
        float o = acc[k] * (1.0f / 3.0f) + bsum + ctr[k * 152];
        dst[(size_t)((row0 + k) * 32 + col) * 64] = o;
    }
}

// ======================================================================
// Kernel 3: 1x1 proj + residual + exact GELU -> g_act
// (R12 version — measured win: 37.5us, occ 83%)
// ======================================================================
__global__ __launch_bounds__(256) void k3_proj_gelu(
    const float* __restrict__ pw, const float* __restrict__ pb)
{
    __shared__ float pws[64 * 65];
    __shared__ __align__(16) float sspt[64 * 34];

    const int tid = threadIdx.x;
    const int b = blockIdx.x >> 5;
    const int pbase = (blockIdx.x & 31) * 32;

    for (int i = tid; i < 4096; i += 256)
        pws[(i >> 6) * 65 + (i & 63)] = pw[i];

    const float* src = g_sp + ((size_t)b * 1024 + pbase) * 64;
    for (int i = tid; i < 2048; i += 256) {
        int pos = i >> 6, cc = i & 63;
        sspt[cc * 34 + pos] = src[i];
    }
    __syncthreads();

    const int c = tid & 63;
    const int pg = tid >> 6;
    unsigned long long acc2[4] = {0ull, 0ull, 0ull, 0ull};

    const float* wr = pws + c * 65;
    const float* yb = sspt + pg * 8;
#pragma unroll 8
    for (int k = 0; k < 64; k++) {
        float wv = wr[k];
        unsigned long long wd = pk2(wv, wv);
        const float* yk = yb + k * 34;
        fma2(acc2[0], *(const unsigned long long*)(yk + 0), wd);
        fma2(acc2[1], *(const unsigned long long*)(yk + 2), wd);
        fma2(acc2[2], *(const unsigned long long*)(yk + 4), wd);
        fma2(acc2[3], *(const unsigned long long*)(yk + 6), wd);
    }

    const float pbv = pb[c];
    float* dst = g_act + ((size_t)b * Nn + 1 + pbase + pg * 8) * 64 + c;
#pragma unroll
    for (int p = 0; p < 4; p++) {
        float a0, a1;
        upk2(acc2[p], a0, a1);
        float r0 = sspt[c * 34 + pg * 8 + 2 * p];
        float r1 = sspt[c * 34 + pg * 8 + 2 * p + 1];
        dst[(size_t)(2 * p) * 64] = gelu_exact(r0 + a0 + pbv);
        dst[(size_t)(2 * p + 1) * 64] = gelu_exact(r1 + a1 + pbv);
    }
}

// CLS token: gelu only
__global__ void k_cls_gelu() {
    int i = blockIdx.x * 256 + threadIdx.x;
    if (i < Bn * Cn) {
        int b = i >> 6, c = i & 63;
        size_t off = (size_t)b * Nn * 64 + c;
        g_act[off] = gelu_exact(g_h[off]);
    }
}

// ======================================================================
// Kernel 4: GEMM2 (g_act @ w2 + b2) + residual x -> out
// (proven 607-config: 128-col chunks, 3 CTAs/SM)
// ======================================================================
#define K4_SMEM (64*128*4 + 64*64*4)

__global__ __launch_bounds__(256, 3) void k4_gemm2(
    const float* __restrict__ x, const float* __restrict__ w2,
    const float* __restrict__ b2, float* __restrict__ out)
{
    extern __shared__ __align__(16) char sm4[];
    float* w2s = (float*)sm4;                      // [64 k][128 c]
    float* sga = (float*)(sm4 + 64 * 128 * 4);     // [64 k][64 r]

    const int tid = threadIdx.x;
    const int rb = blockIdx.x >> 3;
    const int co = (blockIdx.x & 7) * 128;
    const int rowbase = rb * 512;
    const int nsub = (TOT - rowbase < 512) ? ((TOT - rowbase) >> 6) : 8;

#pragma unroll
    for (int i = 0; i < 8; i++) {
        int f = tid + 256 * i;
        int k = f >> 5, c4 = f & 31;
        ((float4*)w2s)[f] = *(const float4*)(w2 + (size_t)k * 1024 + co + c4 * 4);
    }

    const int rg = tid >> 5;
    const int cw = tid & 31;
    const int c0g = co + cw * 4;
    const float4 bv = *(const float4*)(b2 + c0g);

    const int lr = tid >> 2;
    const int lq = tid & 3;

    for (int s2 = 0; s2 < nsub; s2++) {
        __syncthreads();

        {
            int row = rowbase + s2 * 64 + lr;
            int b = row / Nn, n = row - b * Nn;
            const float4* gp = (const float4*)(g_act + ((size_t)b * Nn + n) * 64 + lq * 16);
#pragma unroll
            for (int i = 0; i < 4; i++) {
                float4 g = gp[i];
                int k0 = lq * 16 + i * 4;
                sga[(k0 + 0) * 64 + lr] = g.x;
                sga[(k0 + 1) * 64 + lr] = g.y;
                sga[(k0 + 2) * 64 + lr] = g.z;
                sga[(k0 + 3) * 64 + lr] = g.w;
            }
        }
        __syncthreads();

        unsigned long long acc[4][4];
#pragma unroll
        for (int p = 0; p < 4; p++)
#pragma unroll
            for (int j = 0; j < 4; j++) acc[p][j] = 0ull;

#pragma unroll 4
        for (int k = 0; k < 64; k++) {
            ulonglong2 yA = *(const ulonglong2*)(sga + (k << 6) + (rg << 3));
            ulonglong2 yB = *(const ulonglong2*)(sga + (k << 6) + (rg << 3) + 4);
            float4 w = *(const float4*)(w2s + (k << 7) + (cw << 2));
            unsigned long long w0 = pk2(w.x, w.x), w1d = pk2(w.y, w.y);
            unsigned long long w2d = pk2(w.z, w.z), w3 = pk2(w.w, w.w);
            fma2(acc[0][0], yA.x, w0); fma2(acc[0][1], yA.x, w1d);
            fma2(acc[0][2], yA.x, w2d); fma2(acc[0][3], yA.x, w3);
            fma2(acc[1][0], yA.y, w0); fma2(acc[1][1], yA.y, w1d);
            fma2(acc[1][2], yA.y, w2d); fma2(acc[1][3], yA.y, w3);
            fma2(acc[2][0], yB.x, w0); fma2(acc[2][1], yB.x, w1d);
            fma2(acc[2][2], yB.x, w2d); fma2(acc[2][3], yB.x, w3);
            fma2(acc[3][0], yB.y, w0); fma2(acc[3][1], yB.y, w1d);
            fma2(acc[3][2], yB.y, w2d); fma2(acc[3][3], yB.y, w3);
        }

#pragma unroll
        for (int p = 0; p < 4; p++) {
            int rowe = rowbase + s2 * 64 + rg * 8 + 2 * p;
            float ae[4], ao[4];
#pragma unroll
            for (int j = 0; j < 4; j++) upk2(acc[p][j], ae[j], ao[j]);

            int b = rowe / Nn, n = rowe - b * Nn;
            size_t offe = ((size_t)(n * Bn + b) << 10) + c0g;
            float4 xe = *(const float4*)(x + offe);
            *(float4*)(out + offe) = make_float4(xe.x + bv.x + ae[0], xe.y + bv.y + ae[1],
                                                 xe.z + bv.z + ae[2], xe.w + bv.w + ae[3]);
            int rowo = rowe + 1;
            int b2i = rowo / Nn, n2 = rowo - b2i * Nn;
            size_t offo = ((size_t)(n2 * Bn + b2i) << 10) + c0g;
            float4 xo = *(const float4*)(x + offo);
            *(float4*)(out + offo) = make_float4(xo.x + bv.x + ao[0], xo.y + bv.y + ao[1],
                                                 xo.z + bv.z + ao[2], xo.w + bv.w + ao[3]);
        }
    }
}

// ======================================================================
extern "C" void kernel_launch(void* const* d_in, const int* in_sizes, int n_in,
                              void* d_out, int out_size)
{
    (void)in_sizes; (void)n_in; (void)out_size;
    const float* x     = (const float*)d_in[0];
    const float* ln_w  = (const float*)d_in[1];
    const float* ln_b  = (const float*)d_in[2];
    const float* gamma = (const float*)d_in[3];
    const float* gmx   = (const float*)d_in[4];
    const float* w1    = (const float*)d_in[5];
    const float* b1    = (const float*)d_in[6];
    const float* w2    = (const float*)d_in[7];
    const float* b2    = (const float*)d_in[8];
    const float* dw3w  = (const float*)d_in[9];
    const float* dw3b  = (const float*)d_in[10];
    const float* dw5w  = (const float*)d_in[11];
    const float* dw5b  = (const float*)d_in[12];
    const float* dw7w  = (const float*)d_in[13];
    const float* dw7b  = (const float*)d_in[14];
    const float* projw = (const float*)d_in[15];
    const float* projb = (const float*)d_in[16];
    float* out = (float*)d_out;

    cudaFuncSetAttribute(k1g_gemm1, cudaFuncAttributeMaxDynamicSharedMemorySize, K1G_SMEM);
    cudaFuncSetAttribute(k4_gemm2,  cudaFuncAttributeMaxDynamicSharedMemorySize, K4_SMEM);

    k1y_produce<<<8200, 256>>>(x, ln_w, ln_b, gamma, gmx);
    // 65 row-blocks (1024 rows; last has 64) x 2 col-halves
    k1g_gemm1<<<130, 512, K1G_SMEM>>>(w1, b1);
    k2_dwconv<<<dim3(16, 64), 256>>>(dw3w, dw3b, dw5w, dw5b, dw7w, dw7b);
    k_cls_gelu<<<16, 256>>>();
    k3_proj_gelu<<<2048, 256>>>(projw, projb);
    // 129 row-blocks of 512 rows (last has 64) x 8 col-chunks
    k4_gemm2<<<129 * 8, 256, K4_SMEM>>>(x, w2, b2, out);
}

// round 17
// speedup vs baseline: 1.3665x; 1.3665x over previous
#include <cuda_runtime.h>
#include <math.h>

// Shapes (hardcoded from reference setup_inputs)
#define Bn   64
#define Nn   1025
#define Dn   1024
#define Cn   64
#define TOT  (Bn * Nn)   // 65600 rows

// Scratch (device globals; no runtime allocation)
__device__ __align__(16) float g_h[(size_t)TOT * Cn];         // post LN+GEMM1   (B,N,C)
__device__ __align__(16) float g_sp[(size_t)Bn * 1024 * Cn];  // post depthwise  (B,HW,C)
__device__ __align__(16) float g_act[(size_t)TOT * Cn];       // post proj+gelu  (B,N,C)

// ---------- packed f32x2 helpers ----------
static __device__ __forceinline__ unsigned long long pk2(float a, float b) {
    unsigned long long r;
    asm("mov.b64 %0, {%1,%2};" : "=l"(r) : "f"(a), "f"(b));
    return r;
}
static __device__ __forceinline__ void upk2(unsigned long long v, float& a, float& b) {
    asm("mov.b64 {%0,%1}, %2;" : "=f"(a), "=f"(b) : "l"(v));
}
static __device__ __forceinline__ void fma2(unsigned long long& d, unsigned long long a,
                                            unsigned long long b) {
    asm("fma.rn.f32x2 %0, %1, %2, %0;" : "+l"(d) : "l"(a), "l"(b));
}

static __device__ __forceinline__ float gelu_exact(float t) {
    return 0.5f * t * (1.0f + erff(t * 0.70710678118654752f));
}

// ======================================================================
// Kernel 1: LayerNorm + gamma-mix + GEMM1 (y @ w1 + b1) -> g_h
// (proven R7 config: 8 rows/block, 256 threads, 2 CTAs/SM, 64KB dynamic)
// ======================================================================
#define K1_SMEM (8 * 1024 * 8)

__global__ __launch_bounds__(256, 2) void k1_ln_gemm1(
    const float* __restrict__ x, const float* __restrict__ lnw, const float* __restrict__ lnb,
    const float* __restrict__ gam, const float* __restrict__ gmx,
    const float* __restrict__ w1, const float* __restrict__ b1)
{
    extern __shared__ __align__(16) char sm1[];
    unsigned long long* syd = (unsigned long long*)sm1;   // [8][1024]
    __shared__ float2 red8[8][8];

    const int tid = threadIdx.x;
    const int row0 = blockIdx.x * 8;

    int bb[8], nn[8];
#pragma unroll
    for (int r = 0; r < 8; r++) {
        int row = row0 + r;
        bb[r] = row / Nn;
        nn[r] = row - bb[r] * Nn;
    }

    // ---- load x rows (each thread: d-slice tid*4..+3 of all 8 rows) ----
    float4 v[8];
    float s[8], q[8];
#pragma unroll
    for (int r = 0; r < 8; r++) {
        const float4* p = (const float4*)(x + ((size_t)(nn[r] * Bn + bb[r]) << 10));
        float4 t = p[tid];
        v[r] = t;
        s[r] = t.x + t.y + t.z + t.w;
        q[r] = t.x * t.x + t.y * t.y + t.z * t.z + t.w * t.w;
    }
#pragma unroll
    for (int o = 16; o; o >>= 1) {
#pragma unroll
        for (int r = 0; r < 8; r++) {
            s[r] += __shfl_xor_sync(0xffffffffu, s[r], o);
            q[r] += __shfl_xor_sync(0xffffffffu, q[r], o);
        }
    }
    const int wid = tid >> 5;
    if ((tid & 31) == 0) {
#pragma unroll
        for (int r = 0; r < 8; r++) red8[r][wid] = make_float2(s[r], q[r]);
    }
    __syncthreads();

    float mu[8], rs[8];
#pragma unroll
    for (int r = 0; r < 8; r++) {
        float a = 0.f, c = 0.f;
#pragma unroll
        for (int w = 0; w < 8; w++) { a += red8[r][w].x; c += red8[r][w].y; }
        mu[r] = a * (1.0f / 1024.0f);
        float var = c * (1.0f / 1024.0f) - mu[r] * mu[r];
        rs[r] = rsqrtf(var + 1e-5f);
    }

    // ---- y = (ln*gamma) + x*gammax, duplicated, layout [row][k] ----
    const float4 lw = ((const float4*)lnw)[tid];
    const float4 lb = ((const float4*)lnb)[tid];
    const float4 gm = ((const float4*)gam)[tid];
    const float4 gx = ((const float4*)gmx)[tid];
#pragma unroll
    for (int r = 0; r < 8; r++) {
        float4 t = v[r];
        float y0 = ((t.x - mu[r]) * rs[r] * lw.x + lb.x) * gm.x + t.x * gx.x;
        float y1 = ((t.y - mu[r]) * rs[r] * lw.y + lb.y) * gm.y + t.y * gx.y;
        float y2 = ((t.z - mu[r]) * rs[r] * lw.z + lb.z) * gm.z + t.z * gx.z;
        float y3 = ((t.w - mu[r]) * rs[r] * lw.w + lb.w) * gm.w + t.w * gx.w;
        unsigned long long* dst = syd + r * 1024 + tid * 4;
        dst[0] = pk2(y0, y0);
        dst[1] = pk2(y1, y1);
        dst[2] = pk2(y2, y2);
        dst[3] = pk2(y3, y3);
    }
    __syncthreads();

    // ---- GEMM: thread = (kgroup of 64 d) x (4 cols) x 8 rows ----
    const int gidx = tid >> 4;       // 0..15 -> d in [gidx*64, +64)
    const int cq = tid & 15;         // cols cq*4..+3
    const int c0 = cq * 4;
    unsigned long long acc[8][2];
#pragma unroll
    for (int r = 0; r < 8; r++) { acc[r][0] = 0ull; acc[r][1] = 0ull; }

    const float4* w1p = (const float4*)w1;
    const int dbase = gidx * 64;
#pragma unroll 4
    for (int dd = 0; dd < 64; dd++) {
        int d = dbase + dd;
        float4 w = w1p[d * 16 + cq];
        unsigned long long wl = pk2(w.x, w.y), wh = pk2(w.z, w.w);
#pragma unroll
        for (int r = 0; r < 8; r++) {
            unsigned long long yy = syd[r * 1024 + d];
            fma2(acc[r][0], yy, wl);
            fma2(acc[r][1], yy, wh);
        }
    }
    __syncthreads();

    // ---- cross-kgroup reduction (reuse syd as float buffer, 32KB) ----
    float* red = (float*)syd;   // [16 groups][8 rows][64 c]
#pragma unroll
    for (int r = 0; r < 8; r++) {
        float a0, a1, a2, a3;
        upk2(acc[r][0], a0, a1);
        upk2(acc[r][1], a2, a3);
        *(float4*)(red + (gidx * 512 + r * 64 + c0)) = make_float4(a0, a1, a2, a3);
    }
    __syncthreads();

#pragma unroll
    for (int h = 0; h < 2; h++) {
        int o = h * 256 + tid;          // 0..511
        int r = o >> 6, c = o & 63;
        float sum = b1[c];
#pragma unroll
        for (int g = 0; g < 16; g++) sum += red[g * 512 + o];
        g_h[((size_t)bb[r] * Nn + nn[r]) * 64 + c] = sum;
    }
}

// ======================================================================
// Kernel 2: depthwise 3x3 + 5x5 + 7x7, averaged, + identity -> g_sp
// (proven R7 version)
// ======================================================================
__global__ __launch_bounds__(256) void k2_dwconv(
    const float* __restrict__ w3, const float* __restrict__ b3,
    const float* __restrict__ w5, const float* __restrict__ b5,
    const float* __restrict__ w7, const float* __restrict__ b7)
{
    __shared__ __align__(16) float tile[38 * 38 * 4];
    __shared__ float wk[4 * 83];

    const int tid = threadIdx.x;
    const int cg = blockIdx.x;
    const int b = blockIdx.y;

    for (int i = tid; i < 4 * 83; i += 256) {
        int ch = i / 83, j = i - ch * 83;
        int c = cg * 4 + ch;
        float wv;
        if (j < 9)       wv = w3[c * 9 + j];
        else if (j < 34) wv = w5[c * 25 + (j - 9)];
        else             wv = w7[c * 49 + (j - 34)];
        wk[i] = wv;
    }

    const float* src = g_h + ((size_t)b * Nn + 1) * 64 + cg * 4;
    for (int idx = tid; idx < 38 * 38; idx += 256) {
        int rr = idx / 38, cc = idx - rr * 38;
        int gy = rr - 3, gxp = cc - 3;
        float4 val = make_float4(0.f, 0.f, 0.f, 0.f);
        if ((unsigned)gy < 32u && (unsigned)gxp < 32u)
            val = *(const float4*)(src + (size_t)(gy * 32 + gxp) * 64);
        *(float4*)&tile[idx * 4] = val;
    }
    __syncthreads();

    const int ch = tid & 3;
    const int col = (tid >> 2) & 31;
    const int row0 = (tid >> 7) * 16;

    float acc[16];
#pragma unroll
    for (int k = 0; k < 16; k++) acc[k] = 0.f;

    const float* wc = wk + ch * 83;

#define CONV_TAPS(RAD, WOFF, KS)                                                   \
    for (int dy = -(RAD); dy <= (RAD); dy++) {                                     \
        for (int dx = -(RAD); dx <= (RAD); dx++) {                                 \
            float wv = wc[(WOFF) + (dy + (RAD)) * (KS) + (dx + (RAD))];            \
            const float* tp = tile + (((row0 + 3 + dy) * 38) + (col + 3 + dx)) * 4 + ch; \
            _Pragma("unroll")                                                      \
            for (int k = 0; k < 16; k++) acc[k] += tp[k * 152] * wv;               \
        }                                                                          \
    }

    CONV_TAPS(1, 0, 3)
    CONV_TAPS(2, 9, 5)
    CONV_TAPS(3, 34, 7)
#undef CONV_TAPS

    const int c = cg * 4 + ch;
    const float bsum = (b3[c] + b5[c] + b7[c]) * (1.0f / 3.0f);
    float* dst = g_sp + ((size_t)b * 1024) * 64 + c;
    const float* ctr = tile + ((row0 + 3) * 38 + col + 3) * 4 + ch;
#pragma unroll
    for (int k = 0; k < 16; k++) {
        float o = acc[k] * (1.0f / 3.0f) + bsum + ctr[k * 152];
        dst[(size_t)((row0 + k) * 32 + col) * 64] = o;
    }
}

// ======================================================================
// Kernel 3: 1x1 proj + residual + exact GELU -> g_act
// (R12 version — measured win: 37.5us, occ 83%) + cls-gelu folded in
// as 16 extra blocks (blockIdx.x >= 2048).
// ======================================================================
__global__ __launch_bounds__(256) void k3_proj_gelu(
    const float* __restrict__ pw, const float* __restrict__ pb)
{
    __shared__ float pws[64 * 65];
    __shared__ __align__(16) float sspt[64 * 34];

    const int tid = threadIdx.x;

    if (blockIdx.x >= 2048) {
        // ---- CLS tokens: gelu(g_h) only ----
        const int i = (blockIdx.x - 2048) * 256 + tid;   // 0..4095
        const int b = i >> 6, c = i & 63;
        const size_t off = (size_t)b * Nn * 64 + c;
        g_act[off] = gelu_exact(g_h[off]);
        return;
    }

    const int b = blockIdx.x >> 5;
    const int pbase = (blockIdx.x & 31) * 32;

    for (int i = tid; i < 4096; i += 256)
        pws[(i >> 6) * 65 + (i & 63)] = pw[i];

    const float* src = g_sp + ((size_t)b * 1024 + pbase) * 64;
    for (int i = tid; i < 2048; i += 256) {
        int pos = i >> 6, cc = i & 63;
        sspt[cc * 34 + pos] = src[i];
    }
    __syncthreads();

    const int c = tid & 63;
    const int pg = tid >> 6;
    unsigned long long acc2[4] = {0ull, 0ull, 0ull, 0ull};

    const float* wr = pws + c * 65;
    const float* yb = sspt + pg * 8;
#pragma unroll 8
    for (int k = 0; k < 64; k++) {
        float wv = wr[k];
        unsigned long long wd = pk2(wv, wv);
        const float* yk = yb + k * 34;
        fma2(acc2[0], *(const unsigned long long*)(yk + 0), wd);
        fma2(acc2[1], *(const unsigned long long*)(yk + 2), wd);
        fma2(acc2[2], *(const unsigned long long*)(yk + 4), wd);
        fma2(acc2[3], *(const unsigned long long*)(yk + 6), wd);
    }

    const float pbv = pb[c];
    float* dst = g_act + ((size_t)b * Nn + 1 + pbase + pg * 8) * 64 + c;
#pragma unroll
    for (int p = 0; p < 4; p++) {
        float a0, a1;
        upk2(acc2[p], a0, a1);
        float r0 = sspt[c * 34 + pg * 8 + 2 * p];
        float r1 = sspt[c * 34 + pg * 8 + 2 * p + 1];
        dst[(size_t)(2 * p) * 64] = gelu_exact(r0 + a0 + pbv);
        dst[(size_t)(2 * p + 1) * 64] = gelu_exact(r1 + a1 + pbv);
    }
}

// ======================================================================
// Kernel 4: GEMM2 (g_act @ w2 + b2) + residual x -> out
// (proven R7 config: 128-col chunks, 3 CTAs/SM, streams 512 rows)
// ======================================================================
#define K4_SMEM (64*128*4 + 64*64*4)

__global__ __launch_bounds__(256, 3) void k4_gemm2(
    const float* __restrict__ x, const float* __restrict__ w2,
    const float* __restrict__ b2, float* __restrict__ out)
{
    extern __shared__ __align__(16) char sm4[];
    float* w2s = (float*)sm4;                      // [64 k][128 c]
    float* sga = (float*)(sm4 + 64 * 128 * 4);     // [64 k][64 r]

    const int tid = threadIdx.x;
    const int rb = blockIdx.x >> 3;
    const int co = (blockIdx.x & 7) * 128;
    const int rowbase = rb * 512;
    const int nsub = (TOT - rowbase < 512) ? ((TOT - rowbase) >> 6) : 8;

#pragma unroll
    for (int i = 0; i < 8; i++) {
        int f = tid + 256 * i;
        int k = f >> 5, c4 = f & 31;
        ((float4*)w2s)[f] = *(const float4*)(w2 + (size_t)k * 1024 + co + c4 * 4);
    }

    const int rg = tid >> 5;
    const int cw = tid & 31;
    const int c0g = co + cw * 4;
    const float4 bv = *(const float4*)(b2 + c0g);

    const int lr = tid >> 2;
    const int lq = tid & 3;

    for (int s2 = 0; s2 < nsub; s2++) {
        __syncthreads();

        {
            int row = rowbase + s2 * 64 + lr;
            int b = row / Nn, n = row - b * Nn;
            const float4* gp = (const float4*)(g_act + ((size_t)b * Nn + n) * 64 + lq * 16);
#pragma unroll
            for (int i = 0; i < 4; i++) {
                float4 g = gp[i];
                int k0 = lq * 16 + i * 4;
                sga[(k0 + 0) * 64 + lr] = g.x;
                sga[(k0 + 1) * 64 + lr] = g.y;
                sga[(k0 + 2) * 64 + lr] = g.z;
                sga[(k0 + 3) * 64 + lr] = g.w;
            }
        }
        __syncthreads();

        unsigned long long acc[4][4];
#pragma unroll
        for (int p = 0; p < 4; p++)
#pragma unroll
            for (int j = 0; j < 4; j++) acc[p][j] = 0ull;

#pragma unroll 4
        for (int k = 0; k < 64; k++) {
            ulonglong2 yA = *(const ulonglong2*)(sga + (k << 6) + (rg << 3));
            ulonglong2 yB = *(const ulonglong2*)(sga + (k << 6) + (rg << 3) + 4);
            float4 w = *(const float4*)(w2s + (k << 7) + (cw << 2));
            unsigned long long w0 = pk2(w.x, w.x), w1d = pk2(w.y, w.y);
            unsigned long long w2d = pk2(w.z, w.z), w3 = pk2(w.w, w.w);
            fma2(acc[0][0], yA.x, w0); fma2(acc[0][1], yA.x, w1d);
            fma2(acc[0][2], yA.x, w2d); fma2(acc[0][3], yA.x, w3);
            fma2(acc[1][0], yA.y, w0); fma2(acc[1][1], yA.y, w1d);
            fma2(acc[1][2], yA.y, w2d); fma2(acc[1][3], yA.y, w3);
            fma2(acc[2][0], yB.x, w0); fma2(acc[2][1], yB.x, w1d);
            fma2(acc[2][2], yB.x, w2d); fma2(acc[2][3], yB.x, w3);
            fma2(acc[3][0], yB.y, w0); fma2(acc[3][1], yB.y, w1d);
            fma2(acc[3][2], yB.y, w2d); fma2(acc[3][3], yB.y, w3);
        }

#pragma unroll
        for (int p = 0; p < 4; p++) {
            int rowe = rowbase + s2 * 64 + rg * 8 + 2 * p;
            float ae[4], ao[4];
#pragma unroll
            for (int j = 0; j < 4; j++) upk2(acc[p][j], ae[j], ao[j]);

            int b = rowe / Nn, n = rowe - b * Nn;
            size_t offe = ((size_t)(n * Bn + b) << 10) + c0g;
            float4 xe = *(const float4*)(x + offe);
            *(float4*)(out + offe) = make_float4(xe.x + bv.x + ae[0], xe.y + bv.y + ae[1],
                                                 xe.z + bv.z + ae[2], xe.w + bv.w + ae[3]);
            int rowo = rowe + 1;
            int b2i = rowo / Nn, n2 = rowo - b2i * Nn;
            size_t offo = ((size_t)(n2 * Bn + b2i) << 10) + c0g;
            float4 xo = *(const float4*)(x + offo);
            *(float4*)(out + offo) = make_float4(xo.x + bv.x + ao[0], xo.y + bv.y + ao[1],
                                                 xo.z + bv.z + ao[2], xo.w + bv.w + ao[3]);
        }
    }
}

// ======================================================================
extern "C" void kernel_launch(void* const* d_in, const int* in_sizes, int n_in,
                              void* d_out, int out_size)
{
    (void)in_sizes; (void)n_in; (void)out_size;
    const float* x     = (const float*)d_in[0];
    const float* ln_w  = (const float*)d_in[1];
    const float* ln_b  = (const float*)d_in[2];
    const float* gamma = (const float*)d_in[3];
    const float* gmx   = (const float*)d_in[4];
    const float* w1    = (const float*)d_in[5];
    const float* b1    = (const float*)d_in[6];
    const float* w2    = (const float*)d_in[7];
    const float* b2    = (const float*)d_in[8];
    const float* dw3w  = (const float*)d_in[9];
    const float* dw3b  = (const float*)d_in[10];
    const float* dw5w  = (const float*)d_in[11];
    const float* dw5b  = (const float*)d_in[12];
    const float* dw7w  = (const float*)d_in[13];
    const float* dw7b  = (const float*)d_in[14];
    const float* projw = (const float*)d_in[15];
    const float* projb = (const float*)d_in[16];
    float* out = (float*)d_out;

    cudaFuncSetAttribute(k1_ln_gemm1, cudaFuncAttributeMaxDynamicSharedMemorySize, K1_SMEM);
    cudaFuncSetAttribute(k4_gemm2,    cudaFuncAttributeMaxDynamicSharedMemorySize, K4_SMEM);

    // 65600 rows = 8200 blocks x 8 rows
    k1_ln_gemm1<<<8200, 256, K1_SMEM>>>(x, ln_w, ln_b, gamma, gmx, w1, b1);
    k2_dwconv<<<dim3(16, 64), 256>>>(dw3w, dw3b, dw5w, dw5b, dw7w, dw7b);
    // 2048 spatial blocks + 16 cls blocks
    k3_proj_gelu<<<2064, 256>>>(projw, projb);
    // 129 row-blocks of 512 rows (last has 64) x 8 col-chunks
    k4_gemm2<<<129 * 8, 256, K4_SMEM>>>(x, w2, b2, out);
}